// round 1
// baseline (speedup 1.0000x reference)
#include <cuda_runtime.h>

#define B_ROWS 8192
#define HDIM   1024
#define PCOLS  384     // [group0: rx|t00|t10 (192)] [group1: rx|t01|t11 (192)]
#define KV     192
#define NACC   2048

// ---------------- device scratch (no allocations allowed) ----------------
__device__ __align__(16) float g_P[B_ROWS * PCOLS];        // 12.6 MB
__device__ __align__(16) float g_V[2 * KV * NACC];         // 3.1 MB
__device__ __align__(16) float g_bias[4096];

// ---------------- helpers ----------------
__device__ __forceinline__ float tf32r(float x) {
    unsigned u; asm("cvt.rna.tf32.f32 %0, %1;" : "=r"(u) : "f"(x));
    return __uint_as_float(u);
}
__device__ __forceinline__ float sigmoid_f(float x) {
    float e; asm("ex2.approx.f32 %0, %1;" : "=f"(e) : "f"(-x * 1.4426950408889634f));
    float r; asm("rcp.approx.f32 %0, %1;" : "=f"(r) : "f"(1.0f + e));
    return r;
}
__device__ __forceinline__ float tanh_f(float x) {
    return fmaf(2.0f, sigmoid_f(2.0f * x), -1.0f);
}
__device__ __forceinline__ void mma_tf32(float* d, const unsigned* a, const unsigned* b) {
    asm volatile(
        "mma.sync.aligned.m16n8k8.row.col.f32.tf32.tf32.f32 "
        "{%0,%1,%2,%3}, {%4,%5,%6,%7}, {%8,%9}, {%0,%1,%2,%3};\n"
        : "+f"(d[0]), "+f"(d[1]), "+f"(d[2]), "+f"(d[3])
        : "r"(a[0]), "r"(a[1]), "r"(a[2]), "r"(a[3]), "r"(b[0]), "r"(b[1]));
}
__device__ __forceinline__ void cp_async16(float* dst, const float* src) {
    unsigned d = (unsigned)__cvta_generic_to_shared(dst);
    asm volatile("cp.async.cg.shared.global [%0], [%1], 16;" :: "r"(d), "l"(src));
}

// ---------------- prep: build V_g (192 x 2048, tf32-rounded) + combined bias ----------------
__global__ void prep_kernel(const float* __restrict__ v_x, const float* __restrict__ v_h0,
                            const float* __restrict__ v_h1, const float* __restrict__ bx,
                            const float* __restrict__ bh) {
    int idx = blockIdx.x * 256 + threadIdx.x;
    if (idx < 4096) g_bias[idx] = bx[idx] + bh[idx];
    int total = 2 * KV * NACC;
    if (idx >= total) return;
    int k = idx & (NACC - 1);
    int r = (idx / NACC) % KV;
    int g = idx / (NACC * KV);
    float val;
    if (r < 64) {
        int n = (k >> 9) * 1024 + g * 512 + (k & 511);   // gate*1024 + g*512 + s
        val = v_x[n * 64 + r];
    } else if (r < 128) {
        val = v_h0[(g * 64 + (r - 64)) * 2048 + k];
    } else {
        val = v_h1[(g * 64 + (r - 128)) * 2048 + k];
    }
    g_V[idx] = tf32r(val);
}

// ---------------- stage 1: P = structured low-rank projections (tf32 MMA) ----------------
#define S1_LDA 20
#define S1_LDW 68
__global__ __launch_bounds__(128) void stage1_kernel(
    const float* __restrict__ x, const float* __restrict__ h,
    const float* __restrict__ u_x, const float* __restrict__ u_h0,
    const float* __restrict__ u_h1) {
    __shared__ float As[128 * S1_LDA];
    __shared__ float Ws[16 * S1_LDW];

    int blk = blockIdx.y;
    int r0  = blockIdx.x * 128;
    const float* Aptr; const float* Wptr; int K; int pcol;
    if      (blk == 0) { Aptr = x;       Wptr = u_x;            K = 1024; pcol = 0;   }
    else if (blk == 1) { Aptr = h;       Wptr = u_h0;           K = 512;  pcol = 64;  }  // t_{0,0}
    else if (blk == 2) { Aptr = h + 512; Wptr = u_h1;           K = 512;  pcol = 128; }  // t_{1,0} (perm)
    else if (blk == 3) { Aptr = h + 512; Wptr = u_h0 + 512*64;  K = 512;  pcol = 256; }  // t_{0,1} (perm)
    else               { Aptr = h;       Wptr = u_h1 + 512*64;  K = 512;  pcol = 320; }  // t_{1,1}

    int t = threadIdx.x;
    int warp = t >> 5, lane = t & 31, g4 = lane >> 2, q = lane & 3;

    float acc[2][8][4];
#pragma unroll
    for (int i = 0; i < 2; i++)
#pragma unroll
        for (int j = 0; j < 8; j++)
#pragma unroll
            for (int l = 0; l < 4; l++) acc[i][j][l] = 0.f;

    int NK = K >> 4;
    float4 aR[4], wR[2];
    {   // prefetch chunk 0
        const float* arow = Aptr + (size_t)(r0 + t) * 1024;
        aR[0] = *(const float4*)(arow + 0);  aR[1] = *(const float4*)(arow + 4);
        aR[2] = *(const float4*)(arow + 8);  aR[3] = *(const float4*)(arow + 12);
        wR[0] = *(const float4*)(Wptr + ((t >> 4)    ) * 64 + (t & 15) * 4);
        wR[1] = *(const float4*)(Wptr + ((t >> 4) + 8) * 64 + (t & 15) * 4);
    }

#pragma unroll 1
    for (int ks = 0; ks < NK; ks++) {
        __syncthreads();
        {   // store prefetched chunk to smem with tf32 rounding
            float* ad = &As[t * S1_LDA];
            ad[0]  = tf32r(aR[0].x); ad[1]  = tf32r(aR[0].y); ad[2]  = tf32r(aR[0].z); ad[3]  = tf32r(aR[0].w);
            ad[4]  = tf32r(aR[1].x); ad[5]  = tf32r(aR[1].y); ad[6]  = tf32r(aR[1].z); ad[7]  = tf32r(aR[1].w);
            ad[8]  = tf32r(aR[2].x); ad[9]  = tf32r(aR[2].y); ad[10] = tf32r(aR[2].z); ad[11] = tf32r(aR[2].w);
            ad[12] = tf32r(aR[3].x); ad[13] = tf32r(aR[3].y); ad[14] = tf32r(aR[3].z); ad[15] = tf32r(aR[3].w);
            int wr = t >> 4, wc = (t & 15) * 4;
            float* w0 = &Ws[wr * S1_LDW + wc];
            w0[0] = tf32r(wR[0].x); w0[1] = tf32r(wR[0].y); w0[2] = tf32r(wR[0].z); w0[3] = tf32r(wR[0].w);
            float* w1 = &Ws[(wr + 8) * S1_LDW + wc];
            w1[0] = tf32r(wR[1].x); w1[1] = tf32r(wR[1].y); w1[2] = tf32r(wR[1].z); w1[3] = tf32r(wR[1].w);
        }
        __syncthreads();
        if (ks + 1 < NK) {
            int koff = (ks + 1) << 4;
            const float* arow = Aptr + (size_t)(r0 + t) * 1024 + koff;
            aR[0] = *(const float4*)(arow + 0);  aR[1] = *(const float4*)(arow + 4);
            aR[2] = *(const float4*)(arow + 8);  aR[3] = *(const float4*)(arow + 12);
            wR[0] = *(const float4*)(Wptr + (koff + (t >> 4)    ) * 64 + (t & 15) * 4);
            wR[1] = *(const float4*)(Wptr + (koff + (t >> 4) + 8) * 64 + (t & 15) * 4);
        }
#pragma unroll
        for (int kk = 0; kk < 2; kk++) {
            int kb = kk * 8;
            unsigned af[2][4], bf[8][2];
#pragma unroll
            for (int mt = 0; mt < 2; mt++) {
                int rr = warp * 32 + mt * 16 + g4;
                af[mt][0] = __float_as_uint(As[rr * S1_LDA + kb + q]);
                af[mt][1] = __float_as_uint(As[(rr + 8) * S1_LDA + kb + q]);
                af[mt][2] = __float_as_uint(As[rr * S1_LDA + kb + q + 4]);
                af[mt][3] = __float_as_uint(As[(rr + 8) * S1_LDA + kb + q + 4]);
            }
#pragma unroll
            for (int nt = 0; nt < 8; nt++) {
                bf[nt][0] = __float_as_uint(Ws[(kb + q) * S1_LDW + nt * 8 + g4]);
                bf[nt][1] = __float_as_uint(Ws[(kb + q + 4) * S1_LDW + nt * 8 + g4]);
            }
#pragma unroll
            for (int mt = 0; mt < 2; mt++)
#pragma unroll
                for (int nt = 0; nt < 8; nt++)
                    mma_tf32(acc[mt][nt], af[mt], bf[nt]);
        }
    }

    // store P (tf32-rounded so stage-2 operands are exact-representable)
#pragma unroll
    for (int mt = 0; mt < 2; mt++) {
        int rr = r0 + warp * 32 + mt * 16 + g4;
#pragma unroll
        for (int nt = 0; nt < 8; nt++) {
            int col = pcol + nt * 8 + 2 * q;
            float2 v0 = make_float2(tf32r(acc[mt][nt][0]), tf32r(acc[mt][nt][1]));
            float2 v1 = make_float2(tf32r(acc[mt][nt][2]), tf32r(acc[mt][nt][3]));
            *(float2*)&g_P[(size_t)rr * PCOLS + col] = v0;
            *(float2*)&g_P[(size_t)(rr + 8) * PCOLS + col] = v1;
            if (blk == 0) {  // rx duplicated into group-1 feature block
                *(float2*)&g_P[(size_t)rr * PCOLS + col + 192] = v0;
                *(float2*)&g_P[(size_t)(rr + 8) * PCOLS + col + 192] = v1;
            }
        }
    }
}

// ---------------- stage 2: preact = P_g @ V_g, fused gate epilogue ----------------
#define S2_LDA 20
#define S2_LDB 260
#define S2_SMEM ((2 * 128 * S2_LDA + 2 * 16 * S2_LDB) * 4)

__global__ __launch_bounds__(256) void stage2_kernel(const float* __restrict__ cin,
                                                     float* __restrict__ out) {
    extern __shared__ float sm[];
    float* Abuf = sm;                       // 2 * 128*20
    float* Bbuf = sm + 2 * 128 * S2_LDA;    // 2 * 16*260

    int r0 = blockIdx.x * 128;
    int s0 = blockIdx.y * 64;
    int g  = blockIdx.z;
    int t = threadIdx.x;
    int warp = t >> 5, lane = t & 31, g4 = lane >> 2, q = lane & 3;
    int wm = warp >> 2, wn = warp & 3;

    const float* Pbase = g_P + g * 192;
    const float* Vbase = g_V + (size_t)g * KV * NACC;

    float acc[4][8][4];
#pragma unroll
    for (int i = 0; i < 4; i++)
#pragma unroll
        for (int j = 0; j < 8; j++)
#pragma unroll
            for (int l = 0; l < 4; l++) acc[i][j][l] = 0.f;

    // B column permutation: cc -> k_global = gate*512 + (s0 + warp_n*16 + u)
    auto issue = [&](int ks, int buf) {
        int k0 = ks * 16;
        float* Ad = Abuf + buf * 128 * S2_LDA;
        float* Bd = Bbuf + buf * 16 * S2_LDB;
#pragma unroll
        for (int i = 0; i < 2; i++) {
            int idx = t + i * 256;
            int row = idx >> 2, qq = idx & 3;
            cp_async16(&Ad[row * S2_LDA + qq * 4],
                       Pbase + (size_t)(r0 + row) * PCOLS + k0 + qq * 4);
        }
#pragma unroll
        for (int i = 0; i < 4; i++) {
            int idx = t + i * 256;
            int k = idx >> 6; int rem = idx & 63; int w = rem >> 2; int qq = rem & 3;
            int kcol = (w & 3) * 512 + s0 + ((w >> 2) << 4) + qq * 4;
            cp_async16(&Bd[k * S2_LDB + w * 16 + qq * 4],
                       Vbase + (size_t)(k0 + k) * NACC + kcol);
        }
        asm volatile("cp.async.commit_group;");
    };

    issue(0, 0);
    int buf = 0;
#pragma unroll 1
    for (int ks = 0; ks < 12; ks++) {
        if (ks + 1 < 12) {
            issue(ks + 1, buf ^ 1);
            asm volatile("cp.async.wait_group 1;");
        } else {
            asm volatile("cp.async.wait_group 0;");
        }
        __syncthreads();
        float* Aa = Abuf + buf * 128 * S2_LDA;
        float* Bb = Bbuf + buf * 16 * S2_LDB;
#pragma unroll
        for (int kk = 0; kk < 2; kk++) {
            int kb = kk * 8;
            unsigned af[4][4], bf[8][2];
#pragma unroll
            for (int mt = 0; mt < 4; mt++) {
                int rr = wm * 64 + mt * 16 + g4;
                af[mt][0] = __float_as_uint(Aa[rr * S2_LDA + kb + q]);
                af[mt][1] = __float_as_uint(Aa[(rr + 8) * S2_LDA + kb + q]);
                af[mt][2] = __float_as_uint(Aa[rr * S2_LDA + kb + q + 4]);
                af[mt][3] = __float_as_uint(Aa[(rr + 8) * S2_LDA + kb + q + 4]);
            }
#pragma unroll
            for (int nt = 0; nt < 8; nt++) {
                int cc = wn * 64 + nt * 8 + g4;
                bf[nt][0] = __float_as_uint(Bb[(kb + q) * S2_LDB + cc]);
                bf[nt][1] = __float_as_uint(Bb[(kb + q + 4) * S2_LDB + cc]);
            }
#pragma unroll
            for (int mt = 0; mt < 4; mt++)
#pragma unroll
                for (int nt = 0; nt < 8; nt++)
                    mma_tf32(acc[mt][nt], af[mt], bf[nt]);
        }
        __syncthreads();
        buf ^= 1;
    }

    // fused epilogue: per thread, all 4 gates of each (row, s) live in its own regs
    float* out_h = out;
    float* out_c = out + (size_t)B_ROWS * HDIM;
    int sbase = s0 + wn * 16;
#pragma unroll
    for (int mt = 0; mt < 4; mt++) {
#pragma unroll
        for (int rh = 0; rh < 2; rh++) {
            int row = r0 + wm * 64 + mt * 16 + g4 + rh * 8;
#pragma unroll
            for (int hi = 0; hi < 2; hi++) {
                float hv2[2], cv2[2];
#pragma unroll
                for (int e = 0; e < 2; e++) {
                    int s = sbase + hi * 8 + 2 * q + e;
                    int ridx = rh * 2 + e;
                    float fp = acc[mt][0 + hi][ridx] + g_bias[0 * 1024 + g * 512 + s];
                    float ip = acc[mt][2 + hi][ridx] + g_bias[1 * 1024 + g * 512 + s];
                    float np = acc[mt][4 + hi][ridx] + g_bias[2 * 1024 + g * 512 + s];
                    float op = acc[mt][6 + hi][ridx] + g_bias[3 * 1024 + g * 512 + s];
                    float cv = cin[(size_t)row * HDIM + g * 512 + s];
                    float fg = sigmoid_f(fp), ig = sigmoid_f(ip), og = sigmoid_f(op);
                    float ng = tanh_f(np);
                    float cn = fg * cv + ig * ng;
                    float hn = og * tanh_f(cn);
                    hv2[e] = hn; cv2[e] = cn;
                }
                size_t off = (size_t)row * HDIM + g * 512 + sbase + hi * 8 + 2 * q;
                *(float2*)&out_h[off] = make_float2(hv2[0], hv2[1]);
                *(float2*)&out_c[off] = make_float2(cv2[0], cv2[1]);
            }
        }
    }
}

// ---------------- launch ----------------
extern "C" void kernel_launch(void* const* d_in, const int* in_sizes, int n_in,
                              void* d_out, int out_size) {
    const float* x    = (const float*)d_in[0];
    const float* h    = (const float*)d_in[1];
    const float* c    = (const float*)d_in[2];
    const float* u_x  = (const float*)d_in[3];
    const float* v_x  = (const float*)d_in[4];
    const float* u_h0 = (const float*)d_in[5];
    const float* v_h0 = (const float*)d_in[6];
    const float* u_h1 = (const float*)d_in[7];
    const float* v_h1 = (const float*)d_in[8];
    const float* bx   = (const float*)d_in[9];
    const float* bh   = (const float*)d_in[10];

    cudaFuncSetAttribute(stage2_kernel, cudaFuncAttributeMaxDynamicSharedMemorySize, S2_SMEM);

    prep_kernel<<<(2 * KV * NACC + 255) / 256, 256>>>(v_x, v_h0, v_h1, bx, bh);
    stage1_kernel<<<dim3(64, 5), 128>>>(x, h, u_x, u_h0, u_h1);
    stage2_kernel<<<dim3(64, 8, 2), 256, S2_SMEM>>>(c, (float*)d_out);
}